// round 1
// baseline (speedup 1.0000x reference)
#include <cuda_runtime.h>
#include <math.h>

// ---------------------------------------------------------------------------
// VectorQuant: rows=131072 x-vectors (L=128) vs K=512 codes.
//   d2 = (x2 - 2*dot) + e2   (mimic reference formula incl. quantization)
//   out0 = embedding[argmin], out1 = out2 = sum((x-e*)^2), entropy of hist.
// Strategy: fused fp32 GEMM + streaming argmin, packed fma.rn.f32x2 over L.
// ---------------------------------------------------------------------------

#define LVEC 128      // vector length
#define KTOT 512      // number of codes
#define TM   128      // rows per block
#define KC   64       // codes per smem chunk
#define NTHREADS 256  // (ty 0..15) x (tx 0..15); thread tile = 8 rows x 4 codes

typedef unsigned long long ull;

__device__ float        d_e2[KTOT];
__device__ unsigned int d_hist[KTOT];

__device__ __forceinline__ void fma2(ull& d, ull a, ull b) {
    asm("fma.rn.f32x2 %0, %1, %2, %0;" : "+l"(d) : "l"(a), "l"(b));
}
__device__ __forceinline__ ull pack2(float x, float y) {
    ull r; asm("mov.b64 %0, {%1, %2};" : "=l"(r) : "f"(x), "f"(y)); return r;
}
__device__ __forceinline__ float2 unpack2(ull v) {
    float x, y; asm("mov.b64 {%0, %1}, %2;" : "=f"(x), "=f"(y) : "l"(v));
    return make_float2(x, y);
}

// smem layout (bytes):
//   xs2 : ull[TM][64]   (x pairs, [row][l2])            65536
//   es2 : ull[64][KC]   (code pairs, [l2][code])        32768
//   e2s : float[KC]                                       256
//   x2p : float[256]                                     1024
//   x2s : float[TM]                                       512
//   shist : uint[KTOT]                                   2048
#define SMEM_BYTES (65536 + 32768 + 256 + 1024 + 512 + 2048)

__global__ void __launch_bounds__(NTHREADS) vq_prep(const float* __restrict__ emb) {
    int k = threadIdx.x + blockIdx.x * blockDim.x;
    if (k < KTOT) {
        d_hist[k] = 0u;
        const float4* e4 = (const float4*)emb + (size_t)k * 32;
        float s = 0.f;
        #pragma unroll
        for (int i = 0; i < 32; ++i) {
            float4 v = e4[i];
            s += v.x * v.x; s += v.y * v.y; s += v.z * v.z; s += v.w * v.w;
        }
        d_e2[k] = s;
    }
}

__global__ void __launch_bounds__(NTHREADS) vq_main(
    const float* __restrict__ x, const float* __restrict__ emb,
    float* __restrict__ out0, float* __restrict__ out1, float* __restrict__ out2)
{
    extern __shared__ char smem[];
    ull (*xs2)[64]  = (ull(*)[64])smem;
    ull (*es2)[KC]  = (ull(*)[KC])(smem + 65536);
    float* e2s      = (float*)(smem + 65536 + 32768);
    float* x2p      = e2s + KC;
    float* x2s      = x2p + 256;
    unsigned int* shist = (unsigned int*)(x2s + TM);

    const int tid = threadIdx.x;
    const int tx = tid & 15, ty = tid >> 4;
    const int row0 = blockIdx.x * TM;

    // ---- load x tile (coalesced float4), build [row][l2] f32x2 pairs, partial x2
    {
        const float4* x4 = (const float4*)(x + (size_t)row0 * LVEC);
        int r = tid & 127;
        int b = tid >> 7;          // 0 or 1
        float px2 = 0.f;
        #pragma unroll
        for (int i = 0; i < 16; ++i) {
            int l4 = b + i * 2;    // float4 index within row
            float4 v = x4[(size_t)r * 32 + l4];
            xs2[r][l4 * 2]     = pack2(v.x, v.y);
            xs2[r][l4 * 2 + 1] = pack2(v.z, v.w);
            px2 += v.x * v.x; px2 += v.y * v.y; px2 += v.z * v.z; px2 += v.w * v.w;
        }
        x2p[tid] = px2;
    }
    for (int s = tid; s < KTOT; s += NTHREADS) shist[s] = 0u;
    __syncthreads();
    if (tid < TM) x2s[tid] = x2p[tid] + x2p[tid + 128];

    float best[8];
    int   bidx[8];
    #pragma unroll
    for (int i = 0; i < 8; ++i) { best[i] = 3.4e38f; bidx[i] = 0; }

    const int r0 = ty * 8, c0 = tx * 4;

    for (int kc = 0; kc < KTOT / KC; ++kc) {
        const int kbase = kc * KC;
        __syncthreads();  // protect es2/e2s reuse (also covers x2s on first iter)
        // ---- load code chunk: [l2][code], conflict-free smem stores
        #pragma unroll
        for (int i = 0; i < 8; ++i) {
            int idx = tid + i * NTHREADS;   // 2048 float4s total
            int c   = idx & 63;
            int l4  = idx >> 6;
            float4 v = ((const float4*)emb)[(size_t)(kbase + c) * 32 + l4];
            es2[l4 * 2][c]     = pack2(v.x, v.y);
            es2[l4 * 2 + 1][c] = pack2(v.z, v.w);
        }
        if (tid < KC) e2s[tid] = d_e2[kbase + tid];
        __syncthreads();

        ull acc[8][4];
        #pragma unroll
        for (int i = 0; i < 8; ++i)
            #pragma unroll
            for (int j = 0; j < 4; ++j) acc[i][j] = 0ull;

        #pragma unroll 4
        for (int l2 = 0; l2 < 64; ++l2) {
            ull ev0 = es2[l2][c0 + 0];
            ull ev1 = es2[l2][c0 + 1];
            ull ev2 = es2[l2][c0 + 2];
            ull ev3 = es2[l2][c0 + 3];
            #pragma unroll
            for (int i = 0; i < 8; ++i) {
                ull xv = xs2[r0 + i][l2];
                fma2(acc[i][0], xv, ev0);
                fma2(acc[i][1], xv, ev1);
                fma2(acc[i][2], xv, ev2);
                fma2(acc[i][3], xv, ev3);
            }
        }

        // ---- streaming argmin update (reference formula + rounding order)
        #pragma unroll
        for (int i = 0; i < 8; ++i) {
            float xsq = x2s[r0 + i];
            #pragma unroll
            for (int j = 0; j < 4; ++j) {
                float2 p  = unpack2(acc[i][j]);
                float dot = __fadd_rn(p.x, p.y);
                float d   = __fadd_rn(__fsub_rn(xsq, __fmul_rn(2.0f, dot)),
                                      e2s[c0 + j]);
                int k = kbase + c0 + j;
                if (d < best[i]) { best[i] = d; bidx[i] = k; }  // first-index ties
            }
        }
    }

    // ---- cross-lane (16 tx) argmin reduce, then outputs
    const unsigned FULL = 0xffffffffu;
    #pragma unroll
    for (int i = 0; i < 8; ++i) {
        float v = best[i];
        int   ix = bidx[i];
        #pragma unroll
        for (int off = 8; off > 0; off >>= 1) {
            float ov = __shfl_down_sync(FULL, v, off, 16);
            int   oi = __shfl_down_sync(FULL, ix, off, 16);
            if (ov < v || (ov == v && oi < ix)) { v = ov; ix = oi; }
        }
        ix = __shfl_sync(FULL, ix, 0, 16);  // broadcast winner to the 16-lane group
        if (tx == 0) atomicAdd(&shist[ix], 1u);

        const int row = row0 + r0 + i;
        const float4* e4 = (const float4*)emb + (size_t)ix * 32;
        float4 e0 = e4[tx * 2], e1 = e4[tx * 2 + 1];
        ((float4*)out0)[(size_t)row * 32 + tx * 2]     = e0;
        ((float4*)out0)[(size_t)row * 32 + tx * 2 + 1] = e1;

        float2 a0 = unpack2(xs2[r0 + i][tx * 4 + 0]);
        float2 a1 = unpack2(xs2[r0 + i][tx * 4 + 1]);
        float2 a2 = unpack2(xs2[r0 + i][tx * 4 + 2]);
        float2 a3 = unpack2(xs2[r0 + i][tx * 4 + 3]);
        float s = 0.f;
        float d0;
        d0 = a0.x - e0.x; s += d0 * d0;  d0 = a0.y - e0.y; s += d0 * d0;
        d0 = a1.x - e0.z; s += d0 * d0;  d0 = a1.y - e0.w; s += d0 * d0;
        d0 = a2.x - e1.x; s += d0 * d0;  d0 = a2.y - e1.y; s += d0 * d0;
        d0 = a3.x - e1.z; s += d0 * d0;  d0 = a3.y - e1.w; s += d0 * d0;
        #pragma unroll
        for (int off = 8; off > 0; off >>= 1)
            s += __shfl_down_sync(FULL, s, off, 16);
        if (tx == 0) { out1[row] = s; out2[row] = s; }
    }

    __syncthreads();
    for (int s = tid; s < KTOT; s += NTHREADS) {
        unsigned c = shist[s];
        if (c) atomicAdd(&d_hist[s], c);
    }
}

__global__ void vq_entropy(float* __restrict__ out_ent, float invRows) {
    __shared__ float red[KTOT];
    int t = threadIdx.x;
    float c = (float)d_hist[t];
    float p = c * invRows;                     // invRows = 2^-17 -> exact
    red[t] = (p > 0.f) ? p * logf(p) : 0.f;
    __syncthreads();
    #pragma unroll
    for (int s = KTOT / 2; s > 0; s >>= 1) {
        if (t < s) red[t] += red[t + s];
        __syncthreads();
    }
    if (t == 0) *out_ent = -red[0];
}

extern "C" void kernel_launch(void* const* d_in, const int* in_sizes, int n_in,
                              void* d_out, int out_size)
{
    const float* x   = (const float*)d_in[0];   // (16,8192,1,128) fp32
    const float* emb = (const float*)d_in[1];   // (1,512,128) fp32
    const int rows = in_sizes[0] / LVEC;        // 131072

    float* out0 = (float*)d_out;                // rows*128
    float* out1 = out0 + (size_t)rows * LVEC;   // rows
    float* out2 = out1 + rows;                  // rows
    float* oent = out2 + rows;                  // 1

    cudaFuncSetAttribute(vq_main, cudaFuncAttributeMaxDynamicSharedMemorySize,
                         SMEM_BYTES);

    vq_prep<<<(KTOT + NTHREADS - 1) / NTHREADS, NTHREADS>>>(emb);
    vq_main<<<rows / TM, NTHREADS, SMEM_BYTES>>>(x, emb, out0, out1, out2);
    vq_entropy<<<1, KTOT>>>(oent, 1.0f / (float)rows);
}